// round 5
// baseline (speedup 1.0000x reference)
#include <cuda_runtime.h>
#include <math.h>
#include <stdint.h>

#define NN 384
#define CD 128
#define NH 4
#define HD 32
#define RR 96
#define SDIM 449
#define MHID 256
#define ZDIM 577   // CD + SDIM
#define NB 8       // mlp rows per block

// ---------------- scratch (device globals; no runtime alloc) ----------------
__device__ float g_xn[NN*NN*CD];        // LayerNormed x
__device__ float g_qkvg[NN*NN*512];     // fused projections [i*N+j][512]
__device__ float g_go[NN*NN*CD];        // gated attention output
__device__ float g_B[NH*NN*NN];         // low-rank bias matrix per head
__device__ float g_rowmean[NN*CD];
__device__ float g_colmean[NN*CD];
__device__ float g_qbias[NH*NN*RR];
__device__ float g_kbias[NH*NN*RR];
__device__ float g_Wcat[CD*512];

__device__ __forceinline__ float warp_sum(float v){
  #pragma unroll
  for(int o=16;o;o>>=1) v += __shfl_xor_sync(0xffffffffu, v, o);
  return v;
}

__device__ __forceinline__ uint32_t f2tf(float f){
  uint32_t u; asm("cvt.rna.tf32.f32 %0, %1;" : "=r"(u) : "f"(f)); return u;
}

__device__ __forceinline__ void mma_tf32(float* c, uint32_t a0, uint32_t a1,
    uint32_t a2, uint32_t a3, uint32_t b0, uint32_t b1){
  asm volatile(
    "mma.sync.aligned.m16n8k8.row.col.f32.tf32.tf32.f32 "
    "{%0,%1,%2,%3},{%4,%5,%6,%7},{%8,%9},{%0,%1,%2,%3};"
    : "+f"(c[0]),"+f"(c[1]),"+f"(c[2]),"+f"(c[3])
    : "r"(a0),"r"(a1),"r"(a2),"r"(a3),"r"(b0),"r"(b1));
}

// ---------------- 1. LayerNorm: one warp per 128-vector ----------------
__global__ __launch_bounds__(256) void ln_kernel(const float* __restrict__ x,
    const float* __restrict__ gamma, const float* __restrict__ beta){
  int w = threadIdx.x >> 5, lane = threadIdx.x & 31;
  size_t vec = (size_t)blockIdx.x*8 + w;
  float4 v = *(const float4*)(x + vec*CD + lane*4);
  float s  = v.x+v.y+v.z+v.w;
  float ss = v.x*v.x+v.y*v.y+v.z*v.z+v.w*v.w;
  s = warp_sum(s); ss = warp_sum(ss);
  float mu  = s*(1.f/CD);
  float var = ss*(1.f/CD) - mu*mu;
  float rstd = rsqrtf(var + 1e-5f);
  float4 gm = *(const float4*)(gamma + lane*4);
  float4 bt = *(const float4*)(beta  + lane*4);
  float4 o;
  o.x = (v.x-mu)*rstd*gm.x + bt.x;
  o.y = (v.y-mu)*rstd*gm.y + bt.y;
  o.z = (v.z-mu)*rstd*gm.z + bt.z;
  o.w = (v.w-mu)*rstd*gm.w + bt.w;
  *(float4*)(g_xn + vec*CD + lane*4) = o;
}

// ---------------- 2. row / col means ----------------
__global__ __launch_bounds__(128) void mean_kernel(){
  int c = threadIdx.x;
  int i = blockIdx.x;
  float s = 0.f;
  if (blockIdx.y == 0){
    for (int j=0;j<NN;++j) s += g_xn[((size_t)i*NN+j)*CD + c];
    g_rowmean[i*CD+c] = s*(1.f/NN);
  } else {
    for (int j=0;j<NN;++j) s += g_xn[((size_t)j*NN+i)*CD + c];
    g_colmean[i*CD+c] = s*(1.f/NN);
  }
}

// ---------------- 3. bias MLPs (8 rows/block: 8x weight reuse) ----------------
__global__ __launch_bounds__(256) void mlp_kernel(const float* __restrict__ s_inputs,
    const float* __restrict__ Wq1, const float* __restrict__ Wq2, const float* __restrict__ Wq3,
    const float* __restrict__ Wk1, const float* __restrict__ Wk2, const float* __restrict__ Wk3){
  __shared__ float z[NB][ZDIM];
  __shared__ float a[NB][MHID];
  __shared__ float b2[NB][MHID];
  int n0 = blockIdx.x*NB, t = threadIdx.x;
  int qpath = (blockIdx.y == 0);
  const float* mean = qpath ? g_rowmean : g_colmean;
  const float* W1 = qpath ? Wq1 : Wk1;
  const float* W2 = qpath ? Wq2 : Wk2;
  const float* W3 = qpath ? Wq3 : Wk3;
  float* outb = qpath ? g_qbias : g_kbias;

  for (int idx = t; idx < NB*CD; idx += 256){
    int r = idx >> 7, c = idx & 127;
    z[r][c] = mean[(n0+r)*CD + c];
  }
  for (int idx = t; idx < NB*SDIM; idx += 256){
    int r = idx / SDIM, c = idx - r*SDIM;
    z[r][CD + c] = s_inputs[(n0+r)*SDIM + c];
  }
  __syncthreads();

  float acc[NB];
  #pragma unroll
  for (int r=0;r<NB;++r) acc[r] = 0.f;
  #pragma unroll 4
  for (int k = 0; k < ZDIM; ++k){
    float w = W1[k*MHID + t];
    #pragma unroll
    for (int r=0;r<NB;++r) acc[r] += z[r][k]*w;
  }
  #pragma unroll
  for (int r=0;r<NB;++r) a[r][t] = tanhf(acc[r]);
  __syncthreads();

  #pragma unroll
  for (int r=0;r<NB;++r) acc[r] = 0.f;
  #pragma unroll 4
  for (int k = 0; k < MHID; ++k){
    float w = W2[k*MHID + t];
    #pragma unroll
    for (int r=0;r<NB;++r) acc[r] += a[r][k]*w;
  }
  #pragma unroll
  for (int r=0;r<NB;++r) b2[r][t] = tanhf(acc[r]);
  __syncthreads();

  for (int m = t; m < NH*RR; m += 256){
    #pragma unroll
    for (int r=0;r<NB;++r) acc[r] = 0.f;
    #pragma unroll 4
    for (int k = 0; k < MHID; ++k){
      float w = W3[k*(NH*RR) + m];
      #pragma unroll
      for (int r=0;r<NB;++r) acc[r] += b2[r][k]*w;
    }
    int h = m / RR, rr = m - h*RR;
    #pragma unroll
    for (int r=0;r<NB;++r)
      outb[((size_t)h*NN + n0+r)*RR + rr] = acc[r];
  }
}

// ---------------- 4. B[h,q,k] = qbias . kbias  (32x32 tiles) ----------------
__global__ __launch_bounds__(256) void biasmat_kernel(){
  __shared__ float qs[32*97];
  __shared__ float ks[32*97];
  int h  = blockIdx.z;
  int q0 = blockIdx.y*32, k0 = blockIdx.x*32;
  int t = threadIdx.x;
  for (int idx=t; idx<32*96; idx+=256){
    int row=idx/96, r=idx-row*96;
    qs[row*97+r] = g_qbias[((size_t)h*NN + q0+row)*RR + r];
    ks[row*97+r] = g_kbias[((size_t)h*NN + k0+row)*RR + r];
  }
  __syncthreads();
  int wq = t>>5, lane = t&31;
  float s[4] = {0.f,0.f,0.f,0.f};
  #pragma unroll 8
  for (int r=0;r<96;++r){
    float kv = ks[lane*97+r];
    #pragma unroll
    for (int j=0;j<4;++j) s[j] += qs[(wq*4+j)*97+r]*kv;
  }
  #pragma unroll
  for (int j=0;j<4;++j)
    g_B[((size_t)h*NN + q0+wq*4+j)*NN + k0+lane] = s[j];
}

// ---------------- 5. concat weights (q scaled by 1/sqrt(DH)) ----------------
__global__ __launch_bounds__(256) void wcat_kernel(const float* __restrict__ Wq,
    const float* __restrict__ Wk, const float* __restrict__ Wv, const float* __restrict__ Wg){
  int idx = blockIdx.x*256 + threadIdx.x;      // 0..65535
  int k = idx >> 9, c = idx & 511;
  float v;
  if      (c < 128) v = Wq[k*128 + c] * 0.17677669529663689f;
  else if (c < 256) v = Wk[k*128 + (c-128)];
  else if (c < 384) v = Wv[k*128 + (c-256)];
  else              v = Wg[k*128 + (c-384)];
  g_Wcat[idx] = v;
}

// ---------------- 6/8. tf32 tensor-core GEMM: C[M,nc]=A[M,128]@W[128,nc] ----
// block tile: 128 rows x 64 cols, 8 warps (each m16 x n64), K fully staged
#define GEMM_SMEM ((128*136 + 128*72)*4)
__global__ __launch_bounds__(256) void gemm_tc(const float* __restrict__ A,
    const float* __restrict__ W, const float* __restrict__ bias,
    float* __restrict__ Cc, int nc){
  extern __shared__ uint32_t gsm[];
  uint32_t* As = gsm;              // [128][136]
  uint32_t* Ws = gsm + 128*136;    // [128][72]
  int t = threadIdx.x, lane = t & 31, w = t >> 5;
  size_t m0 = (size_t)blockIdx.x*128;
  int n0 = blockIdx.y*64;

  #pragma unroll
  for (int l = 0; l < 16; ++l){
    int idx = t + 256*l;
    int row = idx >> 5, seg = idx & 31;
    float4 v = *(const float4*)&A[(m0+row)*128 + seg*4];
    uint32_t* dst = &As[row*136 + seg*4];
    dst[0]=f2tf(v.x); dst[1]=f2tf(v.y); dst[2]=f2tf(v.z); dst[3]=f2tf(v.w);
  }
  #pragma unroll
  for (int l = 0; l < 8; ++l){
    int idx = t + 256*l;
    int row = idx >> 4, seg = idx & 15;
    float4 v = *(const float4*)&W[(size_t)row*nc + n0 + seg*4];
    uint32_t* dst = &Ws[row*72 + seg*4];
    dst[0]=f2tf(v.x); dst[1]=f2tf(v.y); dst[2]=f2tf(v.z); dst[3]=f2tf(v.w);
  }
  __syncthreads();

  int r0 = w*16;
  float acc[8][4];
  #pragma unroll
  for (int nt=0;nt<8;++nt){ acc[nt][0]=0.f;acc[nt][1]=0.f;acc[nt][2]=0.f;acc[nt][3]=0.f; }

  #pragma unroll
  for (int ks = 0; ks < 16; ++ks){
    int arow = r0 + (lane>>2);
    int acol = ks*8 + (lane&3);
    uint32_t a0 = As[arow*136 + acol];
    uint32_t a1 = As[(arow+8)*136 + acol];
    uint32_t a2 = As[arow*136 + acol + 4];
    uint32_t a3 = As[(arow+8)*136 + acol + 4];
    #pragma unroll
    for (int nt = 0; nt < 8; ++nt){
      int bcol = nt*8 + (lane>>2);
      uint32_t b0 = Ws[(ks*8 + (lane&3))*72 + bcol];
      uint32_t b1 = Ws[(ks*8 + (lane&3) + 4)*72 + bcol];
      mma_tf32(acc[nt], a0, a1, a2, a3, b0, b1);
    }
  }

  float bb[16];
  #pragma unroll
  for (int nt = 0; nt < 8; ++nt){
    if (bias){
      float2 t2 = *(const float2*)&bias[n0 + nt*8 + 2*(lane&3)];
      bb[nt*2] = t2.x; bb[nt*2+1] = t2.y;
    } else { bb[nt*2] = 0.f; bb[nt*2+1] = 0.f; }
  }
  #pragma unroll
  for (int nt = 0; nt < 8; ++nt){
    int col = n0 + nt*8 + 2*(lane&3);
    int row = (int)m0 + r0 + (lane>>2);
    float2 o0; o0.x = acc[nt][0]+bb[nt*2]; o0.y = acc[nt][1]+bb[nt*2+1];
    *(float2*)&Cc[(size_t)row*nc + col] = o0;
    float2 o1; o1.x = acc[nt][2]+bb[nt*2]; o1.y = acc[nt][3]+bb[nt*2+1];
    *(float2*)&Cc[(size_t)(row+8)*nc + col] = o1;
  }
}

// ---------------- 7. flash attention, tf32 tensor cores ----------------
// block per (i,h); 8 warps, each warp: 3 m-tiles of 16 queries, flash over
// 6 key chunks of 64. Strides chosen conflict-free per fragment pattern:
// Q/K stride 36 (bank = 4*g4+tg, distinct), V stride 40, P stride 68.
#define QS_STR 36
#define KS_STR 36
#define VS_STR 40
#define PS_STR 68
#define ATTN_SMEM ((NN*QS_STR + NN*KS_STR + NN*VS_STR + 8*16*PS_STR)*4)
__global__ __launch_bounds__(256) void attn_tc(const float* __restrict__ bg){
  extern __shared__ uint32_t sm[];
  uint32_t* Qs = sm;
  uint32_t* Ks = sm + NN*QS_STR;
  uint32_t* Vs = sm + NN*QS_STR + NN*KS_STR;
  uint32_t* Ps = sm + NN*QS_STR + NN*KS_STR + NN*VS_STR;
  int i = blockIdx.x, h = blockIdx.y;
  int t = threadIdx.x, w = t>>5, lane = t&31;
  const float* base = g_qkvg + (size_t)i*NN*512;
  const float* Bh   = g_B + (size_t)h*NN*NN;

  for (int idx = t; idx < NN*HD; idx += 256){
    int j = idx >> 5, d = idx & 31;
    const float* src = base + j*512 + h*HD + d;
    Qs[j*QS_STR + d] = f2tf(src[0]);
    Ks[j*KS_STR + d] = f2tf(src[128]);
    Vs[j*VS_STR + d] = f2tf(src[256]);
  }
  __syncthreads();

  int g4 = lane >> 2;       // groupID (row within tile)
  int tg = lane & 3;        // thread in group
  uint32_t* Pw = Ps + w*16*PS_STR;

  for (int mt = 0; mt < 3; ++mt){
    int q0 = w*48 + mt*16;
    // preload Q fragments for all 4 k-steps (d = 32)
    uint32_t qf[4][4];
    #pragma unroll
    for (int ks = 0; ks < 4; ++ks){
      int c = ks*8 + tg;
      qf[ks][0] = Qs[(q0+g4)*QS_STR + c];
      qf[ks][1] = Qs[(q0+g4+8)*QS_STR + c];
      qf[ks][2] = Qs[(q0+g4)*QS_STR + c + 4];
      qf[ks][3] = Qs[(q0+g4+8)*QS_STR + c + 4];
    }
    float O[4][4];
    #pragma unroll
    for (int dt=0;dt<4;++dt){ O[dt][0]=0.f;O[dt][1]=0.f;O[dt][2]=0.f;O[dt][3]=0.f; }
    float m0r = -1e30f, m1r = -1e30f, l0 = 0.f, l1 = 0.f;

    for (int ch = 0; ch < 6; ++ch){
      int kb = ch*64;
      // prefetch low-rank bias into registers (overlaps with mma below)
      float bq[8][4];
      #pragma unroll
      for (int nt = 0; nt < 8; ++nt){
        int cb = kb + nt*8 + 2*tg;
        float2 b0 = *(const float2*)&Bh[(size_t)(q0+g4)*NN + cb];
        float2 b1 = *(const float2*)&Bh[(size_t)(q0+g4+8)*NN + cb];
        bq[nt][0]=b0.x; bq[nt][1]=b0.y; bq[nt][2]=b1.x; bq[nt][3]=b1.y;
      }
      float s[8][4];
      #pragma unroll
      for (int nt = 0; nt < 8; ++nt){ s[nt][0]=0.f;s[nt][1]=0.f;s[nt][2]=0.f;s[nt][3]=0.f; }
      // S = Q K^T
      #pragma unroll
      for (int ks = 0; ks < 4; ++ks){
        int kc = ks*8 + tg;
        #pragma unroll
        for (int nt = 0; nt < 8; ++nt){
          int krow = kb + nt*8 + g4;
          uint32_t b0 = Ks[krow*KS_STR + kc];
          uint32_t b1 = Ks[krow*KS_STR + kc + 4];
          mma_tf32(s[nt], qf[ks][0], qf[ks][1], qf[ks][2], qf[ks][3], b0, b1);
        }
      }
      // add bias
      #pragma unroll
      for (int nt = 0; nt < 8; ++nt){
        s[nt][0]+=bq[nt][0]; s[nt][1]+=bq[nt][1];
        s[nt][2]+=bq[nt][2]; s[nt][3]+=bq[nt][3];
      }
      // online softmax
      float mx0 = -1e30f, mx1 = -1e30f;
      #pragma unroll
      for (int nt = 0; nt < 8; ++nt){
        mx0 = fmaxf(mx0, fmaxf(s[nt][0], s[nt][1]));
        mx1 = fmaxf(mx1, fmaxf(s[nt][2], s[nt][3]));
      }
      mx0 = fmaxf(mx0, __shfl_xor_sync(0xffffffffu, mx0, 1));
      mx0 = fmaxf(mx0, __shfl_xor_sync(0xffffffffu, mx0, 2));
      mx1 = fmaxf(mx1, __shfl_xor_sync(0xffffffffu, mx1, 1));
      mx1 = fmaxf(mx1, __shfl_xor_sync(0xffffffffu, mx1, 2));
      float nm0 = fmaxf(m0r, mx0), nm1 = fmaxf(m1r, mx1);
      float al0 = __expf(m0r - nm0), al1 = __expf(m1r - nm1);
      m0r = nm0; m1r = nm1;
      float sum0 = 0.f, sum1 = 0.f;
      #pragma unroll
      for (int nt = 0; nt < 8; ++nt){
        float p0 = __expf(s[nt][0] - nm0);
        float p1 = __expf(s[nt][1] - nm0);
        float p2 = __expf(s[nt][2] - nm1);
        float p3 = __expf(s[nt][3] - nm1);
        sum0 += p0 + p1; sum1 += p2 + p3;
        int col = nt*8 + 2*tg;
        Pw[g4*PS_STR + col]   = f2tf(p0);
        Pw[g4*PS_STR + col+1] = f2tf(p1);
        Pw[(g4+8)*PS_STR + col]   = f2tf(p2);
        Pw[(g4+8)*PS_STR + col+1] = f2tf(p3);
      }
      sum0 += __shfl_xor_sync(0xffffffffu, sum0, 1);
      sum0 += __shfl_xor_sync(0xffffffffu, sum0, 2);
      sum1 += __shfl_xor_sync(0xffffffffu, sum1, 1);
      sum1 += __shfl_xor_sync(0xffffffffu, sum1, 2);
      l0 = l0*al0 + sum0; l1 = l1*al1 + sum1;
      #pragma unroll
      for (int dt = 0; dt < 4; ++dt){
        O[dt][0] *= al0; O[dt][1] *= al0;
        O[dt][2] *= al1; O[dt][3] *= al1;
      }
      __syncwarp();
      // O += P V
      #pragma unroll
      for (int ks2 = 0; ks2 < 8; ++ks2){
        int pc = ks2*8 + tg;
        uint32_t a0 = Pw[g4*PS_STR + pc];
        uint32_t a1 = Pw[(g4+8)*PS_STR + pc];
        uint32_t a2 = Pw[g4*PS_STR + pc + 4];
        uint32_t a3 = Pw[(g4+8)*PS_STR + pc + 4];
        #pragma unroll
        for (int dt = 0; dt < 4; ++dt){
          int vrow = kb + ks2*8 + tg;
          int vcol = dt*8 + g4;
          uint32_t b0 = Vs[vrow*VS_STR + vcol];
          uint32_t b1 = Vs[(vrow+4)*VS_STR + vcol];
          mma_tf32(O[dt], a0, a1, a2, a3, b0, b1);
        }
      }
      __syncwarp();
    }
    // epilogue: normalize, gate, store
    float inv0 = 1.f/l0, inv1 = 1.f/l1;
    #pragma unroll
    for (int dt = 0; dt < 4; ++dt){
      int d = dt*8 + 2*tg;
      float2 bgv = *(const float2*)&bg[h*HD + d];
      int row0 = q0 + g4;
      float2 gl0 = *(const float2*)&base[row0*512 + 384 + h*HD + d];
      float gx = 1.f/(1.f+__expf(-(gl0.x + bgv.x)));
      float gy = 1.f/(1.f+__expf(-(gl0.y + bgv.y)));
      float2 o0; o0.x = O[dt][0]*inv0*gx; o0.y = O[dt][1]*inv0*gy;
      *(float2*)&g_go[((size_t)i*NN + row0)*CD + h*HD + d] = o0;
      int row1 = row0 + 8;
      float2 gl1 = *(const float2*)&base[row1*512 + 384 + h*HD + d];
      gx = 1.f/(1.f+__expf(-(gl1.x + bgv.x)));
      gy = 1.f/(1.f+__expf(-(gl1.y + bgv.y)));
      float2 o1; o1.x = O[dt][2]*inv1*gx; o1.y = O[dt][3]*inv1*gy;
      *(float2*)&g_go[((size_t)i*NN + row1)*CD + h*HD + d] = o1;
    }
  }
}

// ---------------- launch ----------------
extern "C" void kernel_launch(void* const* d_in, const int* in_sizes, int n_in,
                              void* d_out, int out_size){
  const float* x        = (const float*)d_in[0];
  const float* s_inputs = (const float*)d_in[1];
  const float* ln_gamma = (const float*)d_in[2];
  const float* ln_beta  = (const float*)d_in[3];
  const float* Wq1 = (const float*)d_in[4];
  const float* Wq2 = (const float*)d_in[5];
  const float* Wq3 = (const float*)d_in[6];
  const float* Wk1 = (const float*)d_in[7];
  const float* Wk2 = (const float*)d_in[8];
  const float* Wk3 = (const float*)d_in[9];
  const float* Wq_att = (const float*)d_in[10];
  const float* Wk_att = (const float*)d_in[11];
  const float* Wv_att = (const float*)d_in[12];
  const float* Wg  = (const float*)d_in[13];
  const float* bg  = (const float*)d_in[14];
  const float* Wo  = (const float*)d_in[15];
  const float* bo  = (const float*)d_in[16];
  float* out = (float*)d_out;

  float *p_xn, *p_qkvg, *p_go, *p_Wcat;
  cudaGetSymbolAddress((void**)&p_xn,   g_xn);
  cudaGetSymbolAddress((void**)&p_qkvg, g_qkvg);
  cudaGetSymbolAddress((void**)&p_go,   g_go);
  cudaGetSymbolAddress((void**)&p_Wcat, g_Wcat);

  cudaFuncSetAttribute(gemm_tc, cudaFuncAttributeMaxDynamicSharedMemorySize, GEMM_SMEM);
  cudaFuncSetAttribute(attn_tc, cudaFuncAttributeMaxDynamicSharedMemorySize, ATTN_SMEM);

  ln_kernel<<<NN*NN/8, 256>>>(x, ln_gamma, ln_beta);
  mean_kernel<<<dim3(NN,2), 128>>>();
  mlp_kernel<<<dim3(NN/NB,2), 256>>>(s_inputs, Wq1, Wq2, Wq3, Wk1, Wk2, Wk3);
  biasmat_kernel<<<dim3(12,12,NH), 256>>>();
  wcat_kernel<<<256, 256>>>(Wq_att, Wk_att, Wv_att, Wg);
  gemm_tc<<<dim3(NN*NN/128, 8), 256, GEMM_SMEM>>>(p_xn, p_Wcat, nullptr, p_qkvg, 512);
  attn_tc<<<dim3(NN, NH), 256, ATTN_SMEM>>>(bg);
  gemm_tc<<<dim3(NN*NN/128, 2), 256, GEMM_SMEM>>>(p_go, Wo, bo, out, CD);
}

// round 9
// speedup vs baseline: 1.1581x; 1.1581x over previous
#include <cuda_runtime.h>
#include <math.h>
#include <stdint.h>

#define NN 384
#define CD 128
#define NH 4
#define HD 32
#define RR 96
#define SDIM 449
#define MHID 256
#define ZDIM 577   // CD + SDIM

// ---------------- scratch (device globals; no runtime alloc) ----------------
__device__ float g_xn[NN*NN*CD];        // LayerNormed x
__device__ float g_qkvg[NN*NN*512];     // fused projections [i*N+j][512]
__device__ float g_go[NN*NN*CD];        // gated attention output
__device__ float g_B[NH*NN*NN];         // low-rank bias matrix per head
__device__ float g_rowmean[NN*CD];
__device__ float g_colmean[NN*CD];
__device__ float g_qbias[NH*NN*RR];
__device__ float g_kbias[NH*NN*RR];
__device__ float g_Wcat[CD*512];

__device__ __forceinline__ float warp_sum(float v){
  #pragma unroll
  for(int o=16;o;o>>=1) v += __shfl_xor_sync(0xffffffffu, v, o);
  return v;
}

__device__ __forceinline__ uint32_t f2tf(float f){
  uint32_t u; asm("cvt.rna.tf32.f32 %0, %1;" : "=r"(u) : "f"(f)); return u;
}

__device__ __forceinline__ void mma_tf32(float* c, uint32_t a0, uint32_t a1,
    uint32_t a2, uint32_t a3, uint32_t b0, uint32_t b1){
  asm volatile(
    "mma.sync.aligned.m16n8k8.row.col.f32.tf32.tf32.f32 "
    "{%0,%1,%2,%3},{%4,%5,%6,%7},{%8,%9},{%0,%1,%2,%3};"
    : "+f"(c[0]),"+f"(c[1]),"+f"(c[2]),"+f"(c[3])
    : "r"(a0),"r"(a1),"r"(a2),"r"(a3),"r"(b0),"r"(b1));
}

// ---------------- 1. LayerNorm: one warp per 128-vector ----------------
__global__ __launch_bounds__(256) void ln_kernel(const float* __restrict__ x,
    const float* __restrict__ gamma, const float* __restrict__ beta){
  int w = threadIdx.x >> 5, lane = threadIdx.x & 31;
  size_t vec = (size_t)blockIdx.x*8 + w;
  float4 v = *(const float4*)(x + vec*CD + lane*4);
  float s  = v.x+v.y+v.z+v.w;
  float ss = v.x*v.x+v.y*v.y+v.z*v.z+v.w*v.w;
  s = warp_sum(s); ss = warp_sum(ss);
  float mu  = s*(1.f/CD);
  float var = ss*(1.f/CD) - mu*mu;
  float rstd = rsqrtf(var + 1e-5f);
  float4 gm = *(const float4*)(gamma + lane*4);
  float4 bt = *(const float4*)(beta  + lane*4);
  float4 o;
  o.x = (v.x-mu)*rstd*gm.x + bt.x;
  o.y = (v.y-mu)*rstd*gm.y + bt.y;
  o.z = (v.z-mu)*rstd*gm.z + bt.z;
  o.w = (v.w-mu)*rstd*gm.w + bt.w;
  *(float4*)(g_xn + vec*CD + lane*4) = o;
}

// ---------------- 2. row / col means ----------------
__global__ __launch_bounds__(128) void mean_kernel(){
  int c = threadIdx.x;
  int i = blockIdx.x;
  float s = 0.f;
  if (blockIdx.y == 0){
    for (int j=0;j<NN;++j) s += g_xn[((size_t)i*NN+j)*CD + c];
    g_rowmean[i*CD+c] = s*(1.f/NN);
  } else {
    for (int j=0;j<NN;++j) s += g_xn[((size_t)j*NN+i)*CD + c];
    g_colmean[i*CD+c] = s*(1.f/NN);
  }
}

// ---------------- 3. bias MLPs (merged q/k, 4-way ILP; R4 version) ----------
__global__ __launch_bounds__(256) void mlp_kernel(const float* __restrict__ s_inputs,
    const float* __restrict__ Wq1, const float* __restrict__ Wq2, const float* __restrict__ Wq3,
    const float* __restrict__ Wk1, const float* __restrict__ Wk2, const float* __restrict__ Wk3){
  __shared__ float z[ZDIM];
  __shared__ float a[MHID];
  __shared__ float b[MHID];
  int n = blockIdx.x, t = threadIdx.x;
  int qpath = (blockIdx.y == 0);
  const float* mean = qpath ? g_rowmean : g_colmean;
  const float* W1 = qpath ? Wq1 : Wk1;
  const float* W2 = qpath ? Wq2 : Wk2;
  const float* W3 = qpath ? Wq3 : Wk3;
  float* outb = qpath ? g_qbias : g_kbias;
  if (t < CD) z[t] = mean[n*CD + t];
  for (int idx = t; idx < SDIM; idx += 256) z[CD+idx] = s_inputs[n*SDIM + idx];
  __syncthreads();
  float a0=0.f,a1=0.f,a2=0.f,a3=0.f;
  int k = 0;
  for (; k+3 < ZDIM; k += 4){
    a0 += z[k+0]*W1[(k+0)*MHID + t];
    a1 += z[k+1]*W1[(k+1)*MHID + t];
    a2 += z[k+2]*W1[(k+2)*MHID + t];
    a3 += z[k+3]*W1[(k+3)*MHID + t];
  }
  for (; k < ZDIM; ++k) a0 += z[k]*W1[k*MHID + t];
  a[t] = tanhf((a0+a1)+(a2+a3));
  __syncthreads();
  a0=a1=a2=a3=0.f;
  #pragma unroll 4
  for (k = 0; k < MHID; k += 4){
    a0 += a[k+0]*W2[(k+0)*MHID + t];
    a1 += a[k+1]*W2[(k+1)*MHID + t];
    a2 += a[k+2]*W2[(k+2)*MHID + t];
    a3 += a[k+3]*W2[(k+3)*MHID + t];
  }
  b[t] = tanhf((a0+a1)+(a2+a3));
  __syncthreads();
  for (int m = t; m < NH*RR; m += 256){
    a0=a1=a2=a3=0.f;
    #pragma unroll 4
    for (k = 0; k < MHID; k += 4){
      a0 += b[k+0]*W3[(k+0)*(NH*RR) + m];
      a1 += b[k+1]*W3[(k+1)*(NH*RR) + m];
      a2 += b[k+2]*W3[(k+2)*(NH*RR) + m];
      a3 += b[k+3]*W3[(k+3)*(NH*RR) + m];
    }
    int h = m / RR, r = m % RR;
    outb[((size_t)h*NN + n)*RR + r] = (a0+a1)+(a2+a3);
  }
}

// ---------------- 4. B[h,q,k] = qbias . kbias  (32x32 tiles) ----------------
__global__ __launch_bounds__(256) void biasmat_kernel(){
  __shared__ float qs[32*97];
  __shared__ float ks[32*97];
  int h  = blockIdx.z;
  int q0 = blockIdx.y*32, k0 = blockIdx.x*32;
  int t = threadIdx.x;
  for (int idx=t; idx<32*96; idx+=256){
    int row=idx/96, r=idx-row*96;
    qs[row*97+r] = g_qbias[((size_t)h*NN + q0+row)*RR + r];
    ks[row*97+r] = g_kbias[((size_t)h*NN + k0+row)*RR + r];
  }
  __syncthreads();
  int wq = t>>5, lane = t&31;
  float s[4] = {0.f,0.f,0.f,0.f};
  #pragma unroll 8
  for (int r=0;r<96;++r){
    float kv = ks[lane*97+r];
    #pragma unroll
    for (int j=0;j<4;++j) s[j] += qs[(wq*4+j)*97+r]*kv;
  }
  #pragma unroll
  for (int j=0;j<4;++j)
    g_B[((size_t)h*NN + q0+wq*4+j)*NN + k0+lane] = s[j];
}

// ---------------- 5. concat weights (q scaled by 1/sqrt(DH)) ----------------
__global__ __launch_bounds__(256) void wcat_kernel(const float* __restrict__ Wq,
    const float* __restrict__ Wk, const float* __restrict__ Wv, const float* __restrict__ Wg){
  int idx = blockIdx.x*256 + threadIdx.x;      // 0..65535
  int k = idx >> 9, c = idx & 511;
  float v;
  if      (c < 128) v = Wq[k*128 + c] * 0.17677669529663689f;
  else if (c < 256) v = Wk[k*128 + (c-128)];
  else if (c < 384) v = Wv[k*128 + (c-256)];
  else              v = Wg[k*128 + (c-384)];
  g_Wcat[idx] = v;
}

// ---------------- 6/8. tf32 tensor-core GEMM: C[M,nc]=A[M,128]@W[128,nc] ----
// block tile: 128 rows x 64 cols, 8 warps (each m16 x n64), K fully staged
// As stride 132 (== 4 mod 32): A-fragment LDS banks 4*g4+tg, conflict-free.
#define AS_STR 132
#define GEMM_SMEM ((128*AS_STR + 128*72)*4)
__global__ __launch_bounds__(256) void gemm_tc(const float* __restrict__ A,
    const float* __restrict__ W, const float* __restrict__ bias,
    float* __restrict__ Cc, int nc){
  extern __shared__ uint32_t gsm[];
  uint32_t* As = gsm;              // [128][AS_STR]
  uint32_t* Ws = gsm + 128*AS_STR; // [128][72]
  int t = threadIdx.x, lane = t & 31, w = t >> 5;
  size_t m0 = (size_t)blockIdx.x*128;
  int n0 = blockIdx.y*64;

  #pragma unroll
  for (int l = 0; l < 16; ++l){
    int idx = t + 256*l;
    int row = idx >> 5, seg = idx & 31;
    float4 v = *(const float4*)&A[(m0+row)*128 + seg*4];
    uint32_t* dst = &As[row*AS_STR + seg*4];
    dst[0]=f2tf(v.x); dst[1]=f2tf(v.y); dst[2]=f2tf(v.z); dst[3]=f2tf(v.w);
  }
  #pragma unroll
  for (int l = 0; l < 8; ++l){
    int idx = t + 256*l;
    int row = idx >> 4, seg = idx & 15;
    float4 v = *(const float4*)&W[(size_t)row*nc + n0 + seg*4];
    uint32_t* dst = &Ws[row*72 + seg*4];
    dst[0]=f2tf(v.x); dst[1]=f2tf(v.y); dst[2]=f2tf(v.z); dst[3]=f2tf(v.w);
  }
  __syncthreads();

  int r0 = w*16;
  float acc[8][4];
  #pragma unroll
  for (int nt=0;nt<8;++nt){ acc[nt][0]=0.f;acc[nt][1]=0.f;acc[nt][2]=0.f;acc[nt][3]=0.f; }

  #pragma unroll
  for (int ks = 0; ks < 16; ++ks){
    int arow = r0 + (lane>>2);
    int acol = ks*8 + (lane&3);
    uint32_t a0 = As[arow*AS_STR + acol];
    uint32_t a1 = As[(arow+8)*AS_STR + acol];
    uint32_t a2 = As[arow*AS_STR + acol + 4];
    uint32_t a3 = As[(arow+8)*AS_STR + acol + 4];
    #pragma unroll
    for (int nt = 0; nt < 8; ++nt){
      int bcol = nt*8 + (lane>>2);
      uint32_t b0 = Ws[(ks*8 + (lane&3))*72 + bcol];
      uint32_t b1 = Ws[(ks*8 + (lane&3) + 4)*72 + bcol];
      mma_tf32(acc[nt], a0, a1, a2, a3, b0, b1);
    }
  }

  float bb[16];
  #pragma unroll
  for (int nt = 0; nt < 8; ++nt){
    if (bias){
      float2 t2 = *(const float2*)&bias[n0 + nt*8 + 2*(lane&3)];
      bb[nt*2] = t2.x; bb[nt*2+1] = t2.y;
    } else { bb[nt*2] = 0.f; bb[nt*2+1] = 0.f; }
  }
  #pragma unroll
  for (int nt = 0; nt < 8; ++nt){
    int col = n0 + nt*8 + 2*(lane&3);
    int row = (int)m0 + r0 + (lane>>2);
    float2 o0; o0.x = acc[nt][0]+bb[nt*2]; o0.y = acc[nt][1]+bb[nt*2+1];
    *(float2*)&Cc[(size_t)row*nc + col] = o0;
    float2 o1; o1.x = acc[nt][2]+bb[nt*2]; o1.y = acc[nt][3]+bb[nt*2+1];
    *(float2*)&Cc[(size_t)(row+8)*nc + col] = o1;
  }
}

// ---------------- 7. flash attention, tf32 tensor cores ----------------
// block per (i,h); 8 warps x 3 m-tiles of 16 queries, 6 key chunks of 64.
// Q/K stride 36 (bank 4*g4+tg conflict-free), V stride 40, P stride 68.
// Bias B initializes the mma accumulators (R4 structure).
#define QS_STR 36
#define KS_STR 36
#define VS_STR 40
#define PS_STR 68
#define ATTN_SMEM ((NN*QS_STR + NN*KS_STR + NN*VS_STR + 8*16*PS_STR)*4)
__global__ __launch_bounds__(256) void attn_tc(const float* __restrict__ bg){
  extern __shared__ uint32_t sm[];
  uint32_t* Qs = sm;
  uint32_t* Ks = sm + NN*QS_STR;
  uint32_t* Vs = sm + NN*QS_STR + NN*KS_STR;
  uint32_t* Ps = sm + NN*QS_STR + NN*KS_STR + NN*VS_STR;
  int i = blockIdx.x, h = blockIdx.y;
  int t = threadIdx.x, w = t>>5, lane = t&31;
  const float* base = g_qkvg + (size_t)i*NN*512;
  const float* Bh   = g_B + (size_t)h*NN*NN;

  for (int idx = t; idx < NN*HD; idx += 256){
    int j = idx >> 5, d = idx & 31;
    const float* src = base + j*512 + h*HD + d;
    Qs[j*QS_STR + d] = f2tf(src[0]);
    Ks[j*KS_STR + d] = f2tf(src[128]);
    Vs[j*VS_STR + d] = f2tf(src[256]);
  }
  __syncthreads();

  int g4 = lane >> 2;       // groupID (row within tile)
  int tg = lane & 3;        // thread in group
  uint32_t* Pw = Ps + w*16*PS_STR;

  for (int mt = 0; mt < 3; ++mt){
    int q0 = w*48 + mt*16;
    // preload Q fragments for all 4 k-steps (d = 32)
    uint32_t qf[4][4];
    #pragma unroll
    for (int ks = 0; ks < 4; ++ks){
      int c = ks*8 + tg;
      qf[ks][0] = Qs[(q0+g4)*QS_STR + c];
      qf[ks][1] = Qs[(q0+g4+8)*QS_STR + c];
      qf[ks][2] = Qs[(q0+g4)*QS_STR + c + 4];
      qf[ks][3] = Qs[(q0+g4+8)*QS_STR + c + 4];
    }
    float O[4][4];
    #pragma unroll
    for (int dt=0;dt<4;++dt){ O[dt][0]=0.f;O[dt][1]=0.f;O[dt][2]=0.f;O[dt][3]=0.f; }
    float m0r = -1e30f, m1r = -1e30f, l0 = 0.f, l1 = 0.f;

    for (int ch = 0; ch < 6; ++ch){
      int kb = ch*64;
      float s[8][4];
      // init scores with low-rank bias B (accumulator init, R4 style)
      #pragma unroll
      for (int nt = 0; nt < 8; ++nt){
        int cb = kb + nt*8 + 2*tg;
        float2 b0 = *(const float2*)&Bh[(size_t)(q0+g4)*NN + cb];
        float2 b1 = *(const float2*)&Bh[(size_t)(q0+g4+8)*NN + cb];
        s[nt][0]=b0.x; s[nt][1]=b0.y; s[nt][2]=b1.x; s[nt][3]=b1.y;
      }
      // S += Q K^T
      #pragma unroll
      for (int ks = 0; ks < 4; ++ks){
        int kc = ks*8 + tg;
        #pragma unroll
        for (int nt = 0; nt < 8; ++nt){
          int krow = kb + nt*8 + g4;
          uint32_t b0 = Ks[krow*KS_STR + kc];
          uint32_t b1 = Ks[krow*KS_STR + kc + 4];
          mma_tf32(s[nt], qf[ks][0], qf[ks][1], qf[ks][2], qf[ks][3], b0, b1);
        }
      }
      // online softmax
      float mx0 = -1e30f, mx1 = -1e30f;
      #pragma unroll
      for (int nt = 0; nt < 8; ++nt){
        mx0 = fmaxf(mx0, fmaxf(s[nt][0], s[nt][1]));
        mx1 = fmaxf(mx1, fmaxf(s[nt][2], s[nt][3]));
      }
      mx0 = fmaxf(mx0, __shfl_xor_sync(0xffffffffu, mx0, 1));
      mx0 = fmaxf(mx0, __shfl_xor_sync(0xffffffffu, mx0, 2));
      mx1 = fmaxf(mx1, __shfl_xor_sync(0xffffffffu, mx1, 1));
      mx1 = fmaxf(mx1, __shfl_xor_sync(0xffffffffu, mx1, 2));
      float nm0 = fmaxf(m0r, mx0), nm1 = fmaxf(m1r, mx1);
      float al0 = __expf(m0r - nm0), al1 = __expf(m1r - nm1);
      m0r = nm0; m1r = nm1;
      float sum0 = 0.f, sum1 = 0.f;
      #pragma unroll
      for (int nt = 0; nt < 8; ++nt){
        float p0 = __expf(s[nt][0] - nm0);
        float p1 = __expf(s[nt][1] - nm0);
        float p2 = __expf(s[nt][2] - nm1);
        float p3 = __expf(s[nt][3] - nm1);
        sum0 += p0 + p1; sum1 += p2 + p3;
        int col = nt*8 + 2*tg;
        Pw[g4*PS_STR + col]   = f2tf(p0);
        Pw[g4*PS_STR + col+1] = f2tf(p1);
        Pw[(g4+8)*PS_STR + col]   = f2tf(p2);
        Pw[(g4+8)*PS_STR + col+1] = f2tf(p3);
      }
      sum0 += __shfl_xor_sync(0xffffffffu, sum0, 1);
      sum0 += __shfl_xor_sync(0xffffffffu, sum0, 2);
      sum1 += __shfl_xor_sync(0xffffffffu, sum1, 1);
      sum1 += __shfl_xor_sync(0xffffffffu, sum1, 2);
      l0 = l0*al0 + sum0; l1 = l1*al1 + sum1;
      #pragma unroll
      for (int dt = 0; dt < 4; ++dt){
        O[dt][0] *= al0; O[dt][1] *= al0;
        O[dt][2] *= al1; O[dt][3] *= al1;
      }
      __syncwarp();
      // O += P V
      #pragma unroll
      for (int ks2 = 0; ks2 < 8; ++ks2){
        int pc = ks2*8 + tg;
        uint32_t a0 = Pw[g4*PS_STR + pc];
        uint32_t a1 = Pw[(g4+8)*PS_STR + pc];
        uint32_t a2 = Pw[g4*PS_STR + pc + 4];
        uint32_t a3 = Pw[(g4+8)*PS_STR + pc + 4];
        #pragma unroll
        for (int dt = 0; dt < 4; ++dt){
          int vrow = kb + ks2*8 + tg;
          int vcol = dt*8 + g4;
          uint32_t b0 = Vs[vrow*VS_STR + vcol];
          uint32_t b1 = Vs[(vrow+4)*VS_STR + vcol];
          mma_tf32(O[dt], a0, a1, a2, a3, b0, b1);
        }
      }
      __syncwarp();
    }
    // epilogue: normalize, gate, store
    float inv0 = 1.f/l0, inv1 = 1.f/l1;
    #pragma unroll
    for (int dt = 0; dt < 4; ++dt){
      int d = dt*8 + 2*tg;
      float2 bgv = *(const float2*)&bg[h*HD + d];
      int row0 = q0 + g4;
      float2 gl0 = *(const float2*)&base[row0*512 + 384 + h*HD + d];
      float gx = 1.f/(1.f+__expf(-(gl0.x + bgv.x)));
      float gy = 1.f/(1.f+__expf(-(gl0.y + bgv.y)));
      float2 o0; o0.x = O[dt][0]*inv0*gx; o0.y = O[dt][1]*inv0*gy;
      *(float2*)&g_go[((size_t)i*NN + row0)*CD + h*HD + d] = o0;
      int row1 = row0 + 8;
      float2 gl1 = *(const float2*)&base[row1*512 + 384 + h*HD + d];
      gx = 1.f/(1.f+__expf(-(gl1.x + bgv.x)));
      gy = 1.f/(1.f+__expf(-(gl1.y + bgv.y)));
      float2 o1; o1.x = O[dt][2]*inv1*gx; o1.y = O[dt][3]*inv1*gy;
      *(float2*)&g_go[((size_t)i*NN + row1)*CD + h*HD + d] = o1;
    }
  }
}

// ---------------- launch ----------------
extern "C" void kernel_launch(void* const* d_in, const int* in_sizes, int n_in,
                              void* d_out, int out_size){
  const float* x        = (const float*)d_in[0];
  const float* s_inputs = (const float*)d_in[1];
  const float* ln_gamma = (const float*)d_in[2];
  const float* ln_beta  = (const float*)d_in[3];
  const float* Wq1 = (const float*)d_in[4];
  const float* Wq2 = (const float*)d_in[5];
  const float* Wq3 = (const float*)d_in[6];
  const float* Wk1 = (const float*)d_in[7];
  const float* Wk2 = (const float*)d_in[8];
  const float* Wk3 = (const float*)d_in[9];
  const float* Wq_att = (const float*)d_in[10];
  const float* Wk_att = (const float*)d_in[11];
  const float* Wv_att = (const float*)d_in[12];
  const float* Wg  = (const float*)d_in[13];
  const float* bg  = (const float*)d_in[14];
  const float* Wo  = (const float*)d_in[15];
  const float* bo  = (const float*)d_in[16];
  float* out = (float*)d_out;

  float *p_xn, *p_qkvg, *p_go, *p_Wcat;
  cudaGetSymbolAddress((void**)&p_xn,   g_xn);
  cudaGetSymbolAddress((void**)&p_qkvg, g_qkvg);
  cudaGetSymbolAddress((void**)&p_go,   g_go);
  cudaGetSymbolAddress((void**)&p_Wcat, g_Wcat);

  cudaFuncSetAttribute(gemm_tc, cudaFuncAttributeMaxDynamicSharedMemorySize, GEMM_SMEM);
  cudaFuncSetAttribute(attn_tc, cudaFuncAttributeMaxDynamicSharedMemorySize, ATTN_SMEM);

  ln_kernel<<<NN*NN/8, 256>>>(x, ln_gamma, ln_beta);
  mean_kernel<<<dim3(NN,2), 128>>>();
  mlp_kernel<<<dim3(NN,2), 256>>>(s_inputs, Wq1, Wq2, Wq3, Wk1, Wk2, Wk3);
  biasmat_kernel<<<dim3(12,12,NH), 256>>>();
  wcat_kernel<<<256, 256>>>(Wq_att, Wk_att, Wv_att, Wg);
  gemm_tc<<<dim3(NN*NN/128, 8), 256, GEMM_SMEM>>>(p_xn, p_Wcat, nullptr, p_qkvg, 512);
  attn_tc<<<dim3(NN, NH), 256, ATTN_SMEM>>>(bg);
  gemm_tc<<<dim3(NN*NN/128, 2), 256, GEMM_SMEM>>>(p_go, Wo, bo, out, CD);
}